// round 14
// baseline (speedup 1.0000x reference)
#include <cuda_runtime.h>
#include <cuda_bf16.h>
#include <cstdint>

// ---------------------------------------------------------------------------
// EarthAttention3D: B=2, nW=840, N=144, C=192, H=6, d=32
//   All heavy math on tcgen05 kind::tf32 (sm_103a cubin);
//   SIMT fallback bodies for the plain compute_103 ptxas pass.
// ---------------------------------------------------------------------------

typedef unsigned long long ull;
typedef unsigned int u32;

#if defined(__CUDA_ARCH_FEAT_SM103_ALL) || defined(__CUDA_ARCH_FEAT_SM100_ALL) || \
    defined(__CUDA_ARCH_SPECIFIC__)
#define TC_OK 1
#else
#define TC_OK 0
#endif

#define NW     840
#define NTOK   144
#define DIM    192
#define HEADS  6
#define HDIM   32
#define BATCH  2
#define MTOT   (BATCH*NW*NTOK)          // 241920
#define MTILES (MTOT/128)               // 1890
#define TABLE  3312
#define QSCALE 0.17677669529663687f     // 32^-0.5

__device__ float g_qkv[(size_t)MTOT * 576];   // 557 MB scratch (tf32-rounded)
__device__ float g_att[(size_t)MTOT * DIM];   // 186 MB scratch (tf32-rounded)
__device__ float g_wtf[576 * 192];            // prebaked tf32-swizzled W slabs

// ---------------- generic helpers ----------------
__device__ __forceinline__ u32 smem_u32(const void* p) {
    u32 r; asm("{ .reg .u64 t; cvta.to.shared.u64 t, %1; cvt.u32.u64 %0, t; }"
               : "=r"(r) : "l"(p)); return r;
}

#if TC_OK
// ---------------- tcgen05 helpers (arch-specific only) -----------
__device__ __forceinline__ u32 cvt_tf32(float f) {
    u32 r; asm("cvt.rn.tf32.f32 %0, %1;" : "=r"(r) : "f"(f)); return r;
}
__device__ __forceinline__ void mbar_init(u32 mb, u32 cnt) {
    asm volatile("mbarrier.init.shared.b64 [%0], %1;" :: "r"(mb), "r"(cnt) : "memory");
}
__device__ __forceinline__ void mbar_wait(u32 mb, u32 par) {
    asm volatile(
        "{\n\t.reg .pred P;\n\t"
        "W%=:\n\t"
        "mbarrier.try_wait.parity.acquire.cta.shared::cta.b64 P, [%0], %1, 0x989680;\n\t"
        "@P bra D%=;\n\t"
        "bra W%=;\n\t"
        "D%=:\n\t}"
        :: "r"(mb), "r"(par) : "memory");
}
__device__ __forceinline__ ull mk_desc(u32 addr) {   // SW128 K-major, Blackwell v1
    return ((ull)2 << 61) | ((ull)1 << 46) | ((ull)64 << 32) | ((ull)1 << 16)
         | ((addr >> 4) & 0x3FFFull);
}

#define LDTM32(r, ta) \
    asm volatile( \
        "tcgen05.ld.sync.aligned.32x32b.x32.b32 " \
        "{%0, %1, %2, %3, %4, %5, %6, %7, " \
        " %8, %9, %10, %11, %12, %13, %14, %15, " \
        " %16, %17, %18, %19, %20, %21, %22, %23, " \
        " %24, %25, %26, %27, %28, %29, %30, %31}, [%32];" \
        : "=r"((r)[0]),  "=r"((r)[1]),  "=r"((r)[2]),  "=r"((r)[3]), \
          "=r"((r)[4]),  "=r"((r)[5]),  "=r"((r)[6]),  "=r"((r)[7]), \
          "=r"((r)[8]),  "=r"((r)[9]),  "=r"((r)[10]), "=r"((r)[11]), \
          "=r"((r)[12]), "=r"((r)[13]), "=r"((r)[14]), "=r"((r)[15]), \
          "=r"((r)[16]), "=r"((r)[17]), "=r"((r)[18]), "=r"((r)[19]), \
          "=r"((r)[20]), "=r"((r)[21]), "=r"((r)[22]), "=r"((r)[23]), \
          "=r"((r)[24]), "=r"((r)[25]), "=r"((r)[26]), "=r"((r)[27]), \
          "=r"((r)[28]), "=r"((r)[29]), "=r"((r)[30]), "=r"((r)[31]) \
        : "r"(ta))

#define TMWAIT_LD()  asm volatile("tcgen05.wait::ld.sync.aligned;" ::: "memory")
#define TMF_AFTER()  asm volatile("tcgen05.fence::after_thread_sync;" ::: "memory")
#define TMF_BEFORE() asm volatile("tcgen05.fence::before_thread_sync;" ::: "memory")

#define CPA16(dst, src) \
    asm volatile("cp.async.cg.shared.global [%0], [%1], 16;" :: "r"(dst), "l"(src))
#define CPA_COMMIT() asm volatile("cp.async.commit_group;" ::: "memory")
#define CPA_WAIT0()  asm volatile("cp.async.wait_all;" ::: "memory")

static constexpr u32 IDESC_G  = (1u<<4)|(2u<<7)|(2u<<10)|((64u/8)<<17)|((128u/16)<<24);
static constexpr u32 IDESC_S  = (1u<<4)|(2u<<7)|(2u<<10)|((144u/8)<<17)|((128u/16)<<24);
static constexpr u32 IDESC_PV = (1u<<4)|(2u<<7)|(2u<<10)|((32u/8)<<17)|((128u/16)<<24);

__device__ __forceinline__ void mma_tf32(u32 dt, ull ad, ull bd, u32 idesc, u32 en) {
    asm volatile(
        "{\n\t.reg .pred p;\n\t"
        "setp.ne.u32 p, %4, 0;\n\t"
        "tcgen05.mma.cta_group::1.kind::tf32 [%0], %1, %2, %3, {%5,%5,%5,%5}, p;\n\t}"
        :: "r"(dt), "l"(ad), "l"(bd), "r"(idesc), "r"(en), "r"(0u) : "memory");
}
#endif  // TC_OK

// ---------------------------------------------------------------------------
// wprep: convert W (Ntot x 192 fp32, NT layout) into tf32 SW128 slab layout.
// ---------------------------------------------------------------------------
__global__ void wprep(const float* __restrict__ W, float* __restrict__ Wp, int n)
{
    int idx = blockIdx.x * 256 + threadIdx.x;
    if (idx >= n) return;
#if TC_OK
    int row = idx / 48, c4 = idx - row * 48;
    float4 v = *(const float4*)(W + (size_t)row * 192 + c4 * 4);
    uint4 t;
    t.x = cvt_tf32(v.x); t.y = cvt_tf32(v.y);
    t.z = cvt_tf32(v.z); t.w = cvt_tf32(v.w);
    u32 bo = (u32)((row & 63) * 128 + (c4 & 7) * 16);
    bo ^= (bo >> 3) & 0x70;
    char* dst = (char*)Wp + (size_t)(row >> 6) * 49152 + (c4 >> 3) * 8192 + bo;
    *(uint4*)dst = t;
#endif
}

// ---------------------------------------------------------------------------
// GEMM (NT): C[m,n] = A[m,:192] . W[n,:192] + bias[n]   via tcgen05 tf32.
// ---------------------------------------------------------------------------
#define G_OFF_A   1024u
#define G_OFF_W0  99328u
#define G_OFF_W1  148480u
#define G_SMEM_SZ (197632 + 1024)

#if TC_OK
__device__ __forceinline__ void gtc_epilogue8(u32 tmem, int bufsel, int nsub,
        float* __restrict__ C, const float* __restrict__ bias, int Ntot,
        int bm, int wid, int lane, int rnd_out) {
    const int sp = wid & 3, ch = wid >> 2;
    u32 dt = tmem + (u32)(bufsel * 64 + ch * 32) + ((u32)sp << 21);
    u32 dr[32];
    TMF_AFTER();
    LDTM32(dr, dt);
    TMWAIT_LD();
    TMF_BEFORE();
    int m = bm + sp * 32 + lane;
    float* crow = C + (size_t)m * Ntot + nsub * 64 + ch * 32;
    const float4* b4 = (const float4*)(bias + nsub * 64 + ch * 32);
#pragma unroll
    for (int c = 0; c < 8; c++) {
        float4 bb = b4[c];
        float4 o;
        o.x = __uint_as_float(dr[4 * c + 0]) + bb.x;
        o.y = __uint_as_float(dr[4 * c + 1]) + bb.y;
        o.z = __uint_as_float(dr[4 * c + 2]) + bb.z;
        o.w = __uint_as_float(dr[4 * c + 3]) + bb.w;
        if (rnd_out) {
            o.x = __uint_as_float(cvt_tf32(o.x));
            o.y = __uint_as_float(cvt_tf32(o.y));
            o.z = __uint_as_float(cvt_tf32(o.z));
            o.w = __uint_as_float(cvt_tf32(o.w));
        }
        *(float4*)(crow + 4 * c) = o;
    }
}
#endif  // TC_OK

__global__ __launch_bounds__(256, 1) void gemm_tc(
    const float* __restrict__ A, const float* __restrict__ W,
    const float* __restrict__ Wp, const float* __restrict__ bias,
    float* __restrict__ C, int Ntot, int rnd_out, int a_pre)
{
    extern __shared__ char gsm_raw[];
    u32 sb_raw = smem_u32(gsm_raw);
    u32 sb0 = (sb_raw + 1023u) & ~1023u;
    char* gp = gsm_raw + (sb0 - sb_raw);

    const int tid = threadIdx.x;
    const int bm = blockIdx.x * 128;

#if TC_OK
    const int wid = tid >> 5, lane = tid & 31;
    const int niter = Ntot >> 6;

    if (wid == 0) {
        asm volatile("tcgen05.alloc.cta_group::1.sync.aligned.shared::cta.b32 [%0], %1;"
                     :: "r"(sb0), "r"(128u) : "memory");
        asm volatile("tcgen05.relinquish_alloc_permit.cta_group::1.sync.aligned;");
    }
    if (tid == 0) { mbar_init(sb0 + 16, 1); mbar_init(sb0 + 24, 1); }

    // kick W0 copy (async) first
    {
        const char* wsrc = (const char*)Wp;
#pragma unroll
        for (int j = 0; j < 12; j++) {
            int o = (tid + j * 256) * 16;
            CPA16(sb0 + G_OFF_W0 + (u32)o, wsrc + o);
        }
        CPA_COMMIT();
    }

    // A tile (128 x 192)
    const float* Ab = A + (size_t)bm * 192;
    if (a_pre) {   // data already tf32-rounded: raw cp.async with swizzled dst
#pragma unroll
        for (int j = 0; j < 24; j++) {
            int idx = tid + j * 256;
            int row = idx / 48, c4 = idx - row * 48;
            u32 bo = (u32)(row * 128 + (c4 & 7) * 16);
            bo ^= (bo >> 3) & 0x70;
            CPA16(sb0 + G_OFF_A + (u32)((c4 >> 3) * 16384) + bo,
                  (const char*)Ab + (size_t)row * 768 + c4 * 16);
        }
        CPA_COMMIT();
    } else {
#pragma unroll
        for (int j = 0; j < 24; j++) {
            int idx = tid + j * 256;
            int row = idx / 48, c4 = idx - row * 48;
            float4 v = *(const float4*)(Ab + row * 192 + c4 * 4);
            uint4 t;
            t.x = cvt_tf32(v.x); t.y = cvt_tf32(v.y);
            t.z = cvt_tf32(v.z); t.w = cvt_tf32(v.w);
            u32 bo = (u32)(row * 128 + (c4 & 7) * 16);
            bo ^= (bo >> 3) & 0x70;
            *(uint4*)(gp + G_OFF_A + (c4 >> 3) * 16384 + bo) = t;
        }
    }
    CPA_WAIT0();
    asm volatile("fence.proxy.async.shared::cta;" ::: "memory");
    __syncthreads();

    u32 tmem;
    asm("ld.shared.b32 %0, [%1];" : "=r"(tmem) : "r"(sb0));

    const ull descA = mk_desc(sb0 + G_OFF_A);
    u32 ph0 = 0, ph1 = 0;

    for (int it = 0; it < niter; it++) {
        const int buf = it & 1;
        if (it > 0) {
            CPA_WAIT0();
            asm volatile("fence.proxy.async.shared::cta;" ::: "memory");
            __syncthreads();
        }
        if (tid == 0) {
            ull descW = mk_desc(sb0 + (buf ? G_OFF_W1 : G_OFF_W0));
            u32 dtm = tmem + buf * 64;
#pragma unroll
            for (int k = 0; k < 24; k++)
                mma_tf32(dtm, descA + (k >> 2) * 1024 + (k & 3) * 2,
                              descW + (k >> 2) * 512 + (k & 3) * 2, IDESC_G, (u32)(k > 0));
            asm volatile(
                "tcgen05.commit.cta_group::1.mbarrier::arrive::one.shared::cluster.b64 [%0];"
                :: "r"(sb0 + 16 + buf * 8) : "memory");
        }
        if (it > 0) {
            const int pb = buf ^ 1;
            if (pb == 0) { mbar_wait(sb0 + 16, ph0); ph0 ^= 1; }
            else         { mbar_wait(sb0 + 24, ph1); ph1 ^= 1; }
            if (it + 1 < niter) {
                const char* wsrc = (const char*)Wp + (size_t)(it + 1) * 49152;
                u32 wdst = sb0 + (buf ? G_OFF_W0 : G_OFF_W1);
#pragma unroll
                for (int j = 0; j < 12; j++) {
                    int o = (tid + j * 256) * 16;
                    CPA16(wdst + (u32)o, wsrc + o);
                }
                CPA_COMMIT();
            }
            gtc_epilogue8(tmem, pb, it - 1, C, bias, Ntot, bm, wid, lane, rnd_out);
        } else if (niter > 1) {
            const char* wsrc = (const char*)Wp + 49152;
#pragma unroll
            for (int j = 0; j < 12; j++) {
                int o = (tid + j * 256) * 16;
                CPA16(sb0 + G_OFF_W1 + (u32)o, wsrc + o);
            }
            CPA_COMMIT();
        }
    }
    {
        const int lb = (niter - 1) & 1;
        if (lb == 0) mbar_wait(sb0 + 16, ph0);
        else         mbar_wait(sb0 + 24, ph1);
        gtc_epilogue8(tmem, lb, niter - 1, C, bias, Ntot, bm, wid, lane, rnd_out);
    }
    __syncthreads();
    if (wid == 0)
        asm volatile("tcgen05.dealloc.cta_group::1.sync.aligned.b32 %0, %1;"
                     :: "r"(tmem), "r"(128u));

#else  // --------- SIMT fp32 fallback ----------
    float* As = (float*)gp;
    const float* Ab = A + (size_t)bm * 192;
    for (int i = tid; i < 128 * 48; i += 256)
        ((float4*)As)[i] = ((const float4*)Ab)[i];
    __syncthreads();
    for (int idx = tid; idx < 128 * Ntot; idx += 256) {
        int col = idx >> 7, row = idx & 127;
        const float4* ar = (const float4*)(As + row * 192);
        const float4* wr = (const float4*)(W + (size_t)col * 192);
        float s = 0.f;
#pragma unroll 8
        for (int k = 0; k < 48; k++) {
            float4 a = ar[k], w = wr[k];
            s += a.x * w.x + a.y * w.y + a.z * w.z + a.w * w.w;
        }
        C[(size_t)(bm + row) * Ntot + col] = s + bias[col];
    }
#endif
}

// ---------------------------------------------------------------------------
// tcgen05 attention: one CTA per (b,w), 512 threads, 6 heads, pipelined.
// Round-13 memory map (V = 5x4096 = 20480, the round-10 bug fix) plus the
// exonerated round-11 pipelining:
//  - qk(h+1) cp.async prefetch issued after S-MMA(h) wait (runs under softmax)
//  - V(h+1) staged by 6 idle warps concurrently with O epilogue
//  - 10-warp softmax: warps {0-3,7} chunks 0-2, {8-11,15} chunks 3-4; psums.
// SMEM: hdr 1024 | P 5x18432 @1024 | QK 2x18432 @93184 | V 20480 @130048 |
//       BC 79488 @150528 | psA/psB 1152 @230016 -> end 231168
// ---------------------------------------------------------------------------
#define A_P_OFF   1024u
#define A_QK_OFF  93184u
#define A_V_OFF   130048u
#define A_BC_OFF  150528u
#define A_PS_OFF  230016u
#define ATTN2_SMEM (231168 + 1024)

#if TC_OK
__device__ __forceinline__ int cp6(int c) {   // column part of bias idx, x6
    int jz = c / 72, r = c - jz * 72;
    int jh = r / 12, jw = r - jh * 12;
    return (jz * 1656 + jh * 138 - jw) * 6;
}
#endif

__global__ __launch_bounds__(512, 1) void attn_tc(
    const float* __restrict__ qkv, const float* __restrict__ bias_table,
    const float* __restrict__ mask, float* __restrict__ outp)
{
    extern __shared__ char asm_raw[];
    u32 sb_raw = smem_u32(asm_raw);
    u32 sb0 = (sb_raw + 1023u) & ~1023u;
    char* gp = asm_raw + (sb0 - sb_raw);

    const int tid = threadIdx.x;
    const int w = blockIdx.x >> 1;
    const int b = blockIdx.x & 1;
    const float* gq = qkv + (size_t)(b * NW + w) * NTOK * 576;
    const float* maskb = mask + (size_t)b * NTOK * NTOK;
    float* ga = outp + (size_t)(b * NW + w) * NTOK * DIM;

#if TC_OK
    const int wid = tid >> 5, lane = tid & 31;

    if (wid == 0) {
        asm volatile("tcgen05.alloc.cta_group::1.sync.aligned.shared::cta.b32 [%0], %1;"
                     :: "r"(sb0), "r"(512u) : "memory");
        asm volatile("tcgen05.relinquish_alloc_permit.cta_group::1.sync.aligned;");
    }
    if (tid == 0) mbar_init(sb0 + 16, 1);

    // ---- roles ----
    // A-softmax: wid 0-3 (D1) + wid 7 (D2 tail): chunks 0-2, epilogue owner
    // B-softmax: wid 8-11 (D1) + wid 15 (D2 tail): chunks 3-4
    // V crew: wid 4,5,6,12,13,14 (stages V(h+1) under the epilogue)
    const bool smxA = (wid < 4) || (wid == 7);
    const bool smxB = (wid >= 8 && wid < 12) || (wid == 15);
    const bool tail = (wid == 7 || wid == 15);
    const int sub  = tail ? 3 : (smxA ? wid : wid - 8);
    const int qrow = tail ? 112 + lane : sub * 32 + lane;
    const bool act = (!tail) || (lane >= 16);
    const int dbase = tail ? 144 : 0;
    const u32 lofs = (u32)sub << 21;
    const bool vcrew = (wid == 4 || wid == 5 || wid == 6 ||
                        wid == 12 || wid == 13 || wid == 14);
    const int cwt = vcrew ? ((wid < 8 ? wid - 4 : wid - 9) * 32 + lane) : 0;
    int rp6 = 0;
    {
        int iz = qrow / 72, rm = qrow - iz * 72;
        int ih = rm / 12, iw = rm - ih * 12;
        rp6 = (iz * 828 + ih * 23 + iw + 11) * 6;
    }
    const float* mrow = maskb + qrow * NTOK;
    float* psA = (float*)(gp + A_PS_OFF);
    float* psB = (float*)(gp + A_PS_OFF + 576);

    // ---- prologue: qk(0) cp.async, V(0) raw transpose, bias cache ----
    {
        const char* src = (const char*)gq;
        for (int idx = tid; idx < 1152; idx += 512) {
            int row = idx >> 3, c4 = idx & 7;
            u32 bo = (u32)(row * 128 + c4 * 16);
            bo ^= (bo >> 3) & 0x70;
            CPA16(sb0 + A_QK_OFF + bo, src + (size_t)row * 2304 + c4 * 16);
            CPA16(sb0 + A_QK_OFF + 18432u + bo, src + (size_t)row * 2304 + 768 + c4 * 16);
        }
        CPA_COMMIT();
        for (int idx = tid; idx < 1152; idx += 512) {
            int m = idx % NTOK, d4 = idx / NTOK;
            float4 v = *(const float4*)(gq + (size_t)m * 576 + 384 + d4 * 4);
            char* slab = gp + A_V_OFF + (m >> 5) * 4096;
            u32 colb = (u32)((m & 31) * 4);
#pragma unroll
            for (int j = 0; j < 4; j++) {
                u32 bo = (u32)((d4 * 4 + j) * 128) + colb;
                bo ^= (bo >> 3) & 0x70;
                float val = j == 0 ? v.x : (j == 1 ? v.y : (j == 2 ? v.z : v.w));
                *(u32*)(slab + bo) = __float_as_uint(val);
            }
        }
        float* bc = (float*)(gp + A_BC_OFF);
        for (int idx = tid; idx < TABLE * 6; idx += 512) {
            int i = idx / 6, hh = idx - i * 6;
            bc[idx] = bias_table[(size_t)i * (NW * HEADS) + w * HEADS + hh];
        }
    }
    __syncthreads();

    u32 tmem;
    asm("ld.shared.b32 %0, [%1];" : "=r"(tmem) : "r"(sb0));
    const float* bcf = (const float*)(gp + A_BC_OFF);
    u32 mph = 0;

    for (int h = 0; h < HEADS; h++) {
        // ---- make qk(h) (cp.async) and V(h) (STS, synced last iter) visible ----
        CPA_WAIT0();
        asm volatile("fence.proxy.async.shared::cta;" ::: "memory");
        __syncthreads();

        // ---- S MMAs: D1 (q 0..127) @col0, D2 (q 16..143) @col144 ----
        if (tid == 0) {
            ull qd = mk_desc(sb0 + A_QK_OFF);
            ull kd = mk_desc(sb0 + A_QK_OFF + 18432u);
#pragma unroll
            for (int c = 0; c < 4; c++)
                mma_tf32(tmem, qd + c * 2, kd + c * 2, IDESC_S, (u32)(c > 0));
#pragma unroll
            for (int c = 0; c < 4; c++)
                mma_tf32(tmem + 144, qd + 128 + c * 2, kd + c * 2, IDESC_S, (u32)(c > 0));
            asm volatile(
                "tcgen05.commit.cta_group::1.mbarrier::arrive::one.shared::cluster.b64 [%0];"
                :: "r"(sb0 + 16) : "memory");
        }
        mbar_wait(sb0 + 16, mph & 1); mph++;   // S done -> QK buffer free

        // ---- prefetch qk(h+1) via cp.async (retires under softmax) ----
        if (h + 1 < HEADS) {
            const char* src = (const char*)gq + (h + 1) * 128;
            for (int idx = tid; idx < 1152; idx += 512) {
                int row = idx >> 3, c4 = idx & 7;
                u32 bo = (u32)(row * 128 + c4 * 16);
                bo ^= (bo >> 3) & 0x70;
                CPA16(sb0 + A_QK_OFF + bo, src + (size_t)row * 2304 + c4 * 16);
                CPA16(sb0 + A_QK_OFF + 18432u + bo,
                      src + (size_t)row * 2304 + 768 + c4 * 16);
            }
            CPA_COMMIT();
        }

        // ---- 10-warp register softmax -> P slabs + psums ----
        if (smxA || smxB) {
            TMF_AFTER();
            const float* brp = bcf + rp6 + h;
            const u32 rowb = (u32)(qrow * 128);
            const int c0 = smxA ? 0 : 3, c1 = smxA ? 2 : 4;
            float sum = 0.f;
#pragma unroll
            for (int cc = 0; cc < 5; cc++) {
                if (cc < c0 || cc > c1) continue;
                u32 dr[32];
                LDTM32(dr, tmem + dbase + cc * 32 + lofs);
                TMWAIT_LD();
                if (act) {
                    char* ps = gp + A_P_OFF + cc * 18432;
#pragma unroll
                    for (int j0 = 0; j0 < 32; j0 += 4) {
                        const int c = cc * 32 + j0;
                        if (c < NTOK) {
                            float4 mv = *(const float4*)(mrow + c);
                            float e0 = __expf(fmaf(__uint_as_float(dr[j0+0]), QSCALE, brp[cp6(c+0)] + mv.x));
                            float e1 = __expf(fmaf(__uint_as_float(dr[j0+1]), QSCALE, brp[cp6(c+1)] + mv.y));
                            float e2 = __expf(fmaf(__uint_as_float(dr[j0+2]), QSCALE, brp[cp6(c+2)] + mv.z));
                            float e3 = __expf(fmaf(__uint_as_float(dr[j0+3]), QSCALE, brp[cp6(c+3)] + mv.w));
                            sum += (e0 + e1) + (e2 + e3);
                            u32 t0 = cvt_tf32(e0), t1 = cvt_tf32(e1);
                            u32 t2 = cvt_tf32(e2), t3 = cvt_tf32(e3);
                            u32 o = rowb + (u32)((c & 31) * 4);
                            o ^= (o >> 3) & 0x70;
                            asm volatile("st.shared.v2.b32 [%0], {%1,%2};"
                                         :: "r"(smem_u32(ps) + o), "r"(t0), "r"(t1));
                            u32 o2 = rowb + (u32)(((c + 2) & 31) * 4);
                            o2 ^= (o2 >> 3) & 0x70;
                            asm volatile("st.shared.v2.b32 [%0], {%1,%2};"
                                         :: "r"(smem_u32(ps) + o2), "r"(t2), "r"(t3));
                        }
                    }
                }
            }
            TMF_BEFORE();
            if (act) { if (smxA) psA[qrow] = sum; else psB[qrow] = sum; }
        }
        asm volatile("fence.proxy.async.shared::cta;" ::: "memory");
        __syncthreads();   // P + psums visible

        // ---- PV MMAs (K=144, 18 chunks): O-D1 @288, O-D2 @320 ----
        if (tid == 0) {
            ull pd = mk_desc(sb0 + A_P_OFF);
            ull vd = mk_desc(sb0 + A_V_OFF);
#pragma unroll
            for (int kc = 0; kc < 18; kc++)
                mma_tf32(tmem + 288, pd + (kc >> 2) * 1152 + (kc & 3) * 2,
                                     vd + (kc >> 2) * 256 + (kc & 3) * 2,
                                     IDESC_PV, (u32)(kc > 0));
#pragma unroll
            for (int kc = 0; kc < 18; kc++)
                mma_tf32(tmem + 320, pd + 128 + (kc >> 2) * 1152 + (kc & 3) * 2,
                                     vd + (kc >> 2) * 256 + (kc & 3) * 2,
                                     IDESC_PV, (u32)(kc > 0));
            asm volatile(
                "tcgen05.commit.cta_group::1.mbarrier::arrive::one.shared::cluster.b64 [%0];"
                :: "r"(sb0 + 16) : "memory");
        }
        mbar_wait(sb0 + 16, mph & 1); mph++;   // PV done -> V buffer free

        // ---- V(h+1) staging by crew || O epilogue by softmax-A group ----
        if (vcrew && h + 1 < HEADS) {
            const float* vs = gq + 384 + (h + 1) * 32;
            for (int idx = cwt; idx < 1152; idx += 192) {
                int m = idx % NTOK, d4 = idx / NTOK;
                float4 v = *(const float4*)(vs + (size_t)m * 576 + d4 * 4);
                char* slab = gp + A_V_OFF + (m >> 5) * 4096;
                u32 colb = (u32)((m & 31) * 4);
#pragma unroll
                for (int j = 0; j < 4; j++) {
                    u32 bo = (u32)((d4 * 4 + j) * 128) + colb;
                    bo ^= (bo >> 3) & 0x70;
                    float val = j == 0 ? v.x : (j == 1 ? v.y : (j == 2 ? v.z : v.w));
                    *(u32*)(slab + bo) = __float_as_uint(val);
                }
            }
        }
        if (smxA) {
            TMF_AFTER();
            u32 dr[32];
            LDTM32(dr, tmem + (tail ? 320u : 288u) + lofs);
            TMWAIT_LD();
            TMF_BEFORE();
            if (act) {
                float inv = 1.0f / (psA[qrow] + psB[qrow]);
                float* ob = ga + (size_t)qrow * DIM + h * HDIM;
#pragma unroll
                for (int c = 0; c < 8; c++) {
                    float4 o;
                    o.x = __uint_as_float(cvt_tf32(__uint_as_float(dr[4 * c + 0]) * inv));
                    o.y = __uint_as_float(cvt_tf32(__uint_as_float(dr[4 * c + 1]) * inv));
                    o.z = __uint_as_float(cvt_tf32(__uint_as_float(dr[4 * c + 2]) * inv));
                    o.w = __uint_as_float(cvt_tf32(__uint_as_float(dr[4 * c + 3]) * inv));
                    *(float4*)(ob + 4 * c) = o;
                }
            }
        }
        __syncthreads();   // V(h+1) STS + epilogue complete before next head
    }
    if (wid == 0)
        asm volatile("tcgen05.dealloc.cta_group::1.sync.aligned.b32 %0, %1;"
                     :: "r"(tmem), "r"(512u));

#else  // --------- SIMT fallback ----------
    for (int t = tid; t < HEADS * NTOK; t += 512) {
        int h = t / NTOK, qrow = t - h * NTOK;
        const float* qr = gq + (size_t)qrow * 576 + h * HDIM;
        int iz = qrow / 72, rm = qrow - iz * 72;
        int ih = rm / 12, iw = rm - ih * 12;
        int rp = iz * 828 + ih * 23 + iw + 11;
        float mx = -3.0e38f;
        for (int m = 0; m < NTOK; m++) {
            const float* kr = gq + (size_t)m * 576 + 192 + h * HDIM;
            float s = 0.f;
            for (int d = 0; d < HDIM; d++) s += qr[d] * kr[d];
            int jz = m / 72, rm2 = m - jz * 72;
            int jh = rm2 / 12, jw = rm2 - jh * 12;
            int bi = rp + jz * 1656 + jh * 138 - jw;
            s = s * QSCALE + bias_table[(size_t)bi * (NW * HEADS) + w * HEADS + h]
              + maskb[qrow * NTOK + m];
            mx = fmaxf(mx, s);
        }
        float acc[HDIM];
        for (int d = 0; d < HDIM; d++) acc[d] = 0.f;
        float Z = 0.f;
        for (int m = 0; m < NTOK; m++) {
            const float* kr = gq + (size_t)m * 576 + 192 + h * HDIM;
            float s = 0.f;
            for (int d = 0; d < HDIM; d++) s += qr[d] * kr[d];
            int jz = m / 72, rm2 = m - jz * 72;
            int jh = rm2 / 12, jw = rm2 - jh * 12;
            int bi = rp + jz * 1656 + jh * 138 - jw;
            s = s * QSCALE + bias_table[(size_t)bi * (NW * HEADS) + w * HEADS + h]
              + maskb[qrow * NTOK + m];
            float e = __expf(s - mx);
            Z += e;
            const float* vr = gq + (size_t)m * 576 + 384 + h * HDIM;
            for (int d = 0; d < HDIM; d++) acc[d] += e * vr[d];
        }
        float* ob = ga + (size_t)qrow * DIM + h * HDIM;
        for (int d = 0; d < HDIM; d++) ob[d] = acc[d] / Z;
    }
#endif
}

// ---------------------------------------------------------------------------
extern "C" void kernel_launch(void* const* d_in, const int* in_sizes, int n_in,
                              void* d_out, int out_size)
{
    const float* x    = (const float*)d_in[0];
    const float* mask = (const float*)d_in[1];
    const float* w1   = (const float*)d_in[2];
    const float* b1   = (const float*)d_in[3];
    const float* w2   = (const float*)d_in[4];
    const float* b2   = (const float*)d_in[5];
    const float* bt   = (const float*)d_in[6];
    float* out = (float*)d_out;

    void *qkv_p, *att_p, *wtf_p;
    cudaGetSymbolAddress(&qkv_p, g_qkv);
    cudaGetSymbolAddress(&att_p, g_att);
    cudaGetSymbolAddress(&wtf_p, g_wtf);
    float* qkv = (float*)qkv_p;
    float* att = (float*)att_p;
    float* wtf = (float*)wtf_p;

    cudaFuncSetAttribute(gemm_tc, cudaFuncAttributeMaxDynamicSharedMemorySize, G_SMEM_SZ);
    cudaFuncSetAttribute(attn_tc, cudaFuncAttributeMaxDynamicSharedMemorySize, ATTN2_SMEM);

    // QKV projection: 241920 x 576 x 192 (output tf32-rounded for attn)
    wprep<<<(576 * 48 + 255) / 256, 256>>>(w1, wtf, 576 * 48);
    gemm_tc<<<MTILES, 256, G_SMEM_SZ>>>(x, w1, wtf, b1, qkv, 576, 1, 0);
    // fused attention per (b, w)  (writes tf32-rounded O)
    attn_tc<<<NW * BATCH, 512, ATTN2_SMEM>>>(qkv, bt, mask, att);
    // output projection: 241920 x 192 x 192 (A pre-rounded -> cp.async staging)
    wprep<<<(192 * 48 + 255) / 256, 256>>>(w2, wtf, 192 * 48);
    gemm_tc<<<MTILES, 256, G_SMEM_SZ>>>(att, w2, wtf, b2, out, 192, 0, 1);
}